// round 13
// baseline (speedup 1.0000x reference)
#include <cuda_runtime.h>
#include <cuda_bf16.h>
#include <cstdint>
#include <cstddef>

// Problem shape (fixed by the dataset)
constexpr int B_  = 32;
constexpr int T_  = 1000;
constexpr int C_  = 512;     // K
constexpr int V_  = 2000;    // N (logical)
constexpr int U_  = 100;
constexpr int S_  = 201;
constexpr int M_  = B_ * T_; // 32000
constexpr int NPAD = 2048;
constexpr float NEGF = -1.0e30f;

// GEMM tiling: BM=128 x BN=128 CTA tile, 8 warps (2m x 4n), warp tile 64x32.
// BK=32 (128B rows), 2 stages of 32KB -> 2 CTAs per SM.
constexpr int BM = 128;
constexpr int BN = 128;
constexpr int BK = 32;
constexpr int NSTG = C_ / BK;           // 16 k-stages
constexpr int NTILE = NPAD / BN;        // 16
constexpr int MTILE = M_ / BM;          // 250
constexpr int NPART = NTILE * 4;        // 64 lse partials

// smem: 2 stages x 32KB (A 16K + B 16K), bias after
constexpr int SM_STAGE = 32768;
constexpr int SM_BIAS  = 1024 + 2 * SM_STAGE;        // 66560
constexpr int SM_TOTAL = SM_BIAS + 512;              // 67072 (2 CTAs = 134KB/SM)

// -------- scratch (device globals: no allocations allowed) --------
__device__ __align__(256) float    g_logits[(size_t)M_ * V_];   // 256 MB
__device__ __align__(256) uint32_t g_At[(size_t)M_ * C_];       // tf32 bits (rna)
__device__ __align__(256) uint32_t g_Wt[(size_t)NPAD * C_];     // tf32 bits (rna)
__device__ float  g_pmax[NPART][M_];
__device__ float  g_psum[NPART][M_];
__device__ float  g_lse[M_];
__device__ double g_lsesum[B_];          // per-seq sum of lse over t < len
__device__ double g_ctc_acc;
__device__ double g_cr_acc;

// ===================== PTX helpers =====================
__device__ __forceinline__ uint32_t s2u(const void* p) {
    uint32_t a;
    asm("{ .reg .u64 t; cvta.to.shared.u64 t, %1; cvt.u32.u64 %0, t; }" : "=r"(a) : "l"(p));
    return a;
}
__device__ __forceinline__ void cpasync16(uint32_t dst, const void* src) {
    asm volatile("cp.async.cg.shared.global [%0], [%1], 16;" :: "r"(dst), "l"(src) : "memory");
}
__device__ __forceinline__ void ldsm4(uint32_t* r, uint32_t addr) {
    asm volatile("ldmatrix.sync.aligned.m8n8.x4.shared.b16 {%0,%1,%2,%3}, [%4];"
                 : "=r"(r[0]), "=r"(r[1]), "=r"(r[2]), "=r"(r[3]) : "r"(addr));
}
__device__ __forceinline__ void mma_tf32(float* d, const uint32_t* a, const uint32_t* b) {
    asm volatile(
        "mma.sync.aligned.m16n8k8.row.col.f32.tf32.tf32.f32 "
        "{%0,%1,%2,%3}, {%4,%5,%6,%7}, {%8,%9}, {%0,%1,%2,%3};"
        : "+f"(d[0]), "+f"(d[1]), "+f"(d[2]), "+f"(d[3])
        : "r"(a[0]), "r"(a[1]), "r"(a[2]), "r"(a[3]), "r"(b[0]), "r"(b[1]));
}
__device__ __forceinline__ uint32_t f2tf(float f) {
    uint32_t r;
    asm("cvt.rna.tf32.f32 %0, %1;" : "=r"(r) : "f"(f));
    return r;
}

// ===================== tf32 conversion (rna = unbiased), A+W fused ==========
constexpr int CONV_A_BLKS = (int)((size_t)M_ * C_ / 4 / 256);     // 16000
constexpr int CONV_W_BLKS = (int)((size_t)NPAD * C_ / 4 / 256);   // 1024

__global__ __launch_bounds__(256) void conv_kernel(const float* __restrict__ enc,
                                                   const float* __restrict__ W) {
    if (blockIdx.x == 0) {
        if (threadIdx.x == 0) { g_ctc_acc = 0.0; g_cr_acc = 0.0; }
        if (threadIdx.x < B_) g_lsesum[threadIdx.x] = 0.0;
    }
    if (blockIdx.x < CONV_A_BLKS) {
        size_t i = (size_t)blockIdx.x * 256 + threadIdx.x;
        float4 v = reinterpret_cast<const float4*>(enc)[i];
        uint4 o = make_uint4(f2tf(v.x), f2tf(v.y), f2tf(v.z), f2tf(v.w));
        reinterpret_cast<uint4*>(g_At)[i] = o;
    } else {
        size_t i = (size_t)(blockIdx.x - CONV_A_BLKS) * 256 + threadIdx.x;
        int row = (int)(i >> 7);
        float4 v = make_float4(0.f, 0.f, 0.f, 0.f);
        if (row < V_) v = reinterpret_cast<const float4*>(W)[i];
        uint4 o = make_uint4(f2tf(v.x), f2tf(v.y), f2tf(v.z), f2tf(v.w));
        reinterpret_cast<uint4*>(g_Wt)[i] = o;
    }
}

// ===================== TF32 HMMA GEMM + fused LSE partials =====================
// (R10 configuration: 2 stages, distance-1, 2 CTAs/SM — measured best)
__global__ __launch_bounds__(256, 2) void gemm_tc(const float* __restrict__ bias) {
    extern __shared__ __align__(1024) char smem[];
    const uint32_t sbase = s2u(smem);
    const int tid  = threadIdx.x;
    const int lane = tid & 31;
    const int wid  = tid >> 5;
    const int wm   = (wid >> 2) * 64;
    const int wn   = (wid & 3) * 32;
    const int n0   = blockIdx.x * BN;
    const int m0   = blockIdx.y * BM;

    float* sbias = reinterpret_cast<float*>(smem + SM_BIAS);
    if (tid < BN) sbias[tid] = (n0 + tid < V_) ? __ldg(&bias[n0 + tid]) : 0.f;

    auto issue_loads = [&](int s) {
        const uint32_t buf = sbase + 1024 + (uint32_t)(s & 1) * SM_STAGE;
        const int kt = s * BK;
#pragma unroll
        for (int i = 0; i < 4; i++) {
            int flat = tid + i * 256;
            int row = flat >> 3, cc = flat & 7;
            uint32_t off = (uint32_t)(row * 128 + ((cc * 16) ^ ((row & 7) << 4)));
            cpasync16(buf + off, &g_At[(size_t)(m0 + row) * C_ + kt + cc * 4]);
        }
#pragma unroll
        for (int i = 0; i < 4; i++) {
            int flat = tid + i * 256;
            int row = flat >> 3, cc = flat & 7;
            uint32_t off = (uint32_t)(row * 128 + ((cc * 16) ^ ((row & 7) << 4)));
            cpasync16(buf + 16384 + off, &g_Wt[(size_t)(n0 + row) * C_ + kt + cc * 4]);
        }
        asm volatile("cp.async.commit_group;" ::: "memory");
    };

    float acc[4][4][4];
#pragma unroll
    for (int i = 0; i < 4; i++)
#pragma unroll
        for (int j = 0; j < 4; j++)
#pragma unroll
            for (int e = 0; e < 4; e++) acc[i][j][e] = 0.f;

    const uint32_t xr = (uint32_t)((lane & 7) << 4);
    uint32_t offA[4], offB4[2];
#pragma unroll
    for (int mi = 0; mi < 4; mi++) offA[mi] = (uint32_t)((wm + mi * 16 + (lane & 15)) * 128);
#pragma unroll
    for (int p = 0; p < 2; p++)
        offB4[p] = (uint32_t)((wn + p * 16 + ((lane & 16) >> 1) + (lane & 7)) * 128);
    const uint32_t selA = (uint32_t)(lane & 16);
    const uint32_t selB = (uint32_t)((lane & 8) << 1);

    issue_loads(0);

    for (int s = 0; s < NSTG; s++) {
        asm volatile("cp.async.wait_group 0;" ::: "memory");
        __syncthreads();

        const uint32_t stgA = sbase + 1024 + (uint32_t)(s & 1) * SM_STAGE;
        const uint32_t stgB = stgA + 16384;

        uint32_t fa[4][4], fb[2][2][4];
        auto ldfragB = [&](int ks, int pb) {
            const uint32_t cB = ((uint32_t)(ks * 32) + selB) ^ xr;
#pragma unroll
            for (int p = 0; p < 2; p++) ldsm4(fb[pb][p], stgB + offB4[p] + cB);
        };

        ldfragB(0, 0);
        if (s + 1 < NSTG) issue_loads(s + 1);

#pragma unroll
        for (int ks = 0; ks < 4; ks++) {
            const uint32_t cA = ((uint32_t)(ks * 32) + selA) ^ xr;
#pragma unroll
            for (int mi = 0; mi < 4; mi++) ldsm4(fa[mi], stgA + offA[mi] + cA);
            if (ks < 3) ldfragB(ks + 1, (ks + 1) & 1);
#pragma unroll
            for (int mi = 0; mi < 4; mi++)
#pragma unroll
                for (int nj = 0; nj < 4; nj++)
                    mma_tf32(acc[mi][nj], fa[mi],
                             &fb[ks & 1][nj >> 1][(nj & 1) * 2]);
        }
    }

    // ---- epilogue: bias + direct store + fused row max/sumexp partials ----
    const int pn = blockIdx.x * 4 + (wid & 3);
    const int q  = lane >> 2;
    const int c2 = 2 * (lane & 3);

#pragma unroll
    for (int mi = 0; mi < 4; mi++) {
        float mx0 = NEGF, sm0 = 0.f;
        float mx1 = NEGF, sm1 = 0.f;
#pragma unroll
        for (int nj = 0; nj < 4; nj++) {
            int nloc = wn + nj * 8 + c2;
            int n = n0 + nloc;
            float b0 = sbias[nloc], b1 = sbias[nloc + 1];
            float v00 = acc[mi][nj][0] + b0, v01 = acc[mi][nj][1] + b1;
            float v10 = acc[mi][nj][2] + b0, v11 = acc[mi][nj][3] + b1;
            if (n < V_) {
                int mr = m0 + wm + mi * 16 + q;
                *reinterpret_cast<float2*>(&g_logits[(size_t)mr * V_ + n])       = make_float2(v00, v01);
                *reinterpret_cast<float2*>(&g_logits[(size_t)(mr + 8) * V_ + n]) = make_float2(v10, v11);
                float a = fmaxf(v00, v01);
                if (a > mx0) { sm0 *= __expf(mx0 - a); mx0 = a; }
                sm0 += __expf(v00 - mx0) + __expf(v01 - mx0);
                float b = fmaxf(v10, v11);
                if (b > mx1) { sm1 *= __expf(mx1 - b); mx1 = b; }
                sm1 += __expf(v10 - mx1) + __expf(v11 - mx1);
            }
        }
#pragma unroll
        for (int d = 1; d <= 2; d <<= 1) {
            float mo = __shfl_xor_sync(0xffffffffu, mx0, d);
            float so = __shfl_xor_sync(0xffffffffu, sm0, d);
            float M = fmaxf(mx0, mo);
            sm0 = sm0 * __expf(mx0 - M) + so * __expf(mo - M);
            mx0 = M;
            mo = __shfl_xor_sync(0xffffffffu, mx1, d);
            so = __shfl_xor_sync(0xffffffffu, sm1, d);
            M = fmaxf(mx1, mo);
            sm1 = sm1 * __expf(mx1 - M) + so * __expf(mo - M);
            mx1 = M;
        }
        if ((lane & 3) == 0) {
            int mr = m0 + wm + mi * 16 + q;
            g_pmax[pn][mr]     = mx0;  g_psum[pn][mr]     = sm0;
            g_pmax[pn][mr + 8] = mx1;  g_psum[pn][mr + 8] = sm1;
        }
    }
}

// ===================== LSE combine (+ per-seq lse prefix sums) ==============
__global__ __launch_bounds__(256) void lse_combine_kernel(const int* __restrict__ lens) {
    int m = blockIdx.x * 256 + threadIdx.x;
    if (m >= M_) return;
    float mx = NEGF;
#pragma unroll
    for (int p = 0; p < NPART; p++) mx = fmaxf(mx, g_pmax[p][m]);
    float s = 0.f;
#pragma unroll
    for (int p = 0; p < NPART; p++) s += g_psum[p][m] * __expf(g_pmax[p][m] - mx);
    float val = mx + __logf(s);
    g_lse[m] = val;

    // accumulate S_b = sum of lse over t < len (warp-aggregated double atomics)
    int b = m / T_, t = m % T_;
    double contrib = (t < lens[b]) ? (double)val : 0.0;
    int b0 = __shfl_sync(0xffffffffu, b, 0);
    int b31 = __shfl_sync(0xffffffffu, b, 31);
    if (b0 == b31) {
#pragma unroll
        for (int o = 16; o > 0; o >>= 1)
            contrib += __shfl_down_sync(0xffffffffu, contrib, o);
        if ((threadIdx.x & 31) == 0 && contrib != 0.0) atomicAdd(&g_lsesum[b], contrib);
    } else {
        if (contrib != 0.0) atomicAdd(&g_lsesum[b], contrib);
    }
}

// ===================== fused tail: CTC (blocks 0..31) + KL (rest) ==========
__device__ __forceinline__ float logadd3(float a, float b, float c) {
    float m = fmaxf(a, fmaxf(b, c));
    return m + __logf(__expf(a - m) + __expf(b - m) + __expf(c - m));
}
__device__ __forceinline__ float logadd2(float a, float b) {
    float m = fmaxf(a, b);
    return m + __logf(__expf(a - m) + __expf(b - m));
}

// CTC on RAW logits (lse factored out: logadd(a+c,b+c)=logadd(a,b)+c, so the
// per-step -lse(t) shift is applied once at the end via g_lsesum). Each thread
// gathers only ITS OWN label column; neighbor values (s-1, s-2) come from a
// staged shared ring (written >=3 barriers before being read).
__device__ void ctc_body(int b, const int* __restrict__ targets,
                         const int* __restrict__ lens, const int* __restrict__ tlens) {
    const int s = threadIdx.x;           // 0..255 (states >= S_ are inert)
    const int len = lens[b];

    __shared__ float alpha[2][256 + 4];  // 4-element NEGF pad at the front
    __shared__ float stg[4][256 + 4];    // staged p@ta per slot, NEGF pads
    if (s < 4) {
        alpha[0][s] = NEGF; alpha[1][s] = NEGF;
#pragma unroll
        for (int j = 0; j < 4; j++) stg[j][s] = NEGF;
    }

    const int* tg = &targets[b * U_];
    const bool v0 = (s < S_);
    int e0 = 0;
    if (v0 && (s & 1)) e0 = tg[(s - 1) >> 1];

    // skip flags for states s, s-1, s-2
    bool sk0 = false, sk1 = false, sk2 = false;
    if (s < S_) {
        if (s & 1) {
            int i = (s - 1) >> 1;
            if (s >= 3) sk0 = tg[i] != tg[i - 1];
            if (s >= 5) sk2 = tg[i - 1] != tg[i - 2];
        } else {
            if (s >= 4) sk1 = tg[(s - 2) >> 1] != tg[(s - 4) >> 1];
        }
    }

    const size_t rowbase = (size_t)(b * T_);
    alpha[0][4 + s] = (s < 2) ? g_logits[rowbase * V_ + e0] : NEGF;

    // prefill staging ring (slot jj covers t=1+2jj) + own pB register ring
    float pB[4];
#pragma unroll
    for (int jj = 0; jj < 4; jj++) {
        int ta = 1 + 2 * jj;
        int tb = ta + 1 < T_ ? ta + 1 : T_ - 1;
        stg[jj][4 + s] = v0 ? g_logits[(rowbase + ta) * V_ + e0] : NEGF;
        pB[jj]         = v0 ? g_logits[(rowbase + tb) * V_ + e0] : NEGF;
    }
    __syncthreads();

    int cur = 0;
    for (int t0 = 1; t0 < len; t0 += 8) {
#pragma unroll
        for (int jj = 0; jj < 4; jj++) {
            const int t = t0 + 2 * jj;
            const float p0 = stg[jj][4 + s];
            const float p1 = stg[jj][3 + s];
            const float p2 = stg[jj][2 + s];
            const float* Aa = &alpha[cur][4];
            float a0 = Aa[s], a1 = Aa[s - 1], a2 = Aa[s - 2], a3 = Aa[s - 3], a4 = Aa[s - 4];

            float x0 = logadd3(a0, a1, sk0 ? a2 : NEGF) + p0;
            float x1 = logadd3(a1, a2, sk1 ? a3 : NEGF) + p1;
            float x2 = logadd3(a2, a3, sk2 ? a4 : NEGF) + p2;
            float yf = logadd3(x0, x1, sk0 ? x2 : NEGF) + pB[jj];
            float y  = (t >= len) ? a0 : ((t + 1 >= len) ? x0 : yf);

            alpha[cur ^ 1][4 + s] = y;
            cur ^= 1;
            __syncthreads();

            // refill slot jj for time t+8 (consumed 4 iterations from now)
            int tn = t + 8;
            int ta = tn < T_ ? tn : T_ - 1;
            int tb = tn + 1 < T_ ? tn + 1 : T_ - 1;
            stg[jj][4 + s] = v0 ? g_logits[(rowbase + ta) * V_ + e0] : NEGF;
            pB[jj]         = v0 ? g_logits[(rowbase + tb) * V_ + e0] : NEGF;
        }
    }

    if (s == 0) {
        int e = 2 * tlens[b];
        float ab = alpha[cur][4 + e];
        float al = alpha[cur][4 + (e > 0 ? e - 1 : 0)];
        double loss = g_lsesum[b] - (double)logadd2(ab, al);
        atomicAdd(&g_ctc_acc, loss);
    }
}

__device__ void kl_body(int idx, const int* __restrict__ lens) {
    const int t  = idx % T_;
    const int bp = idx / T_;
    const int lenA = lens[bp], lenB = lens[bp + 16];
    const bool doA = t < lenA, doB = t < lenB;
    if (!doA && !doB) return;

    const size_t rowP = (size_t)bp * T_ + t;
    const size_t rowQ = (size_t)(bp + 16) * T_ + t;
    const float* P = &g_logits[rowP * V_];
    const float* Q = &g_logits[rowQ * V_];
    const float Lp = g_lse[rowP], Lq = g_lse[rowQ];

    float accA = 0.f, accB = 0.f;
#pragma unroll 8
    for (int v = threadIdx.x; v < V_; v += 256) {
        float p = P[v] - Lp;
        float q = Q[v] - Lq;
        float d = q - p;
        accA += __expf(q) * d;
        accB -= __expf(p) * d;
    }
    float c = (doA ? accA : 0.f) + (doB ? accB : 0.f);
    for (int o = 16; o > 0; o >>= 1) c += __shfl_down_sync(0xffffffffu, c, o);
    __shared__ float wsum[8];
    if ((threadIdx.x & 31) == 0) wsum[threadIdx.x >> 5] = c;
    __syncthreads();
    if (threadIdx.x == 0) {
        float tot = 0.f;
#pragma unroll
        for (int w = 0; w < 8; w++) tot += wsum[w];
        atomicAdd(&g_cr_acc, (double)tot);
    }
}

__global__ __launch_bounds__(256) void tail_kernel(const int* __restrict__ targets,
                                                   const int* __restrict__ lens,
                                                   const int* __restrict__ tlens) {
    if (blockIdx.x < (unsigned)B_) ctc_body(blockIdx.x, targets, lens, tlens);
    else                            kl_body(blockIdx.x - B_, lens);
}

// ===================== finalize =====================
__global__ void finalize_kernel(float* out) {
    out[0] = (float)(0.5 * g_ctc_acc);
    out[1] = (float)(0.5 * g_cr_acc);
}

// ===================== launch =====================
extern "C" void kernel_launch(void* const* d_in, const int* in_sizes, int n_in,
                              void* d_out, int out_size) {
    const float* enc     = (const float*)d_in[0];
    const float* W       = (const float*)d_in[1];
    const float* bias    = (const float*)d_in[2];
    const int*   lens    = (const int*)d_in[3];
    const int*   targets = (const int*)d_in[4];
    const int*   tlens   = (const int*)d_in[5];
    float* out = (float*)d_out;

    cudaFuncSetAttribute(gemm_tc, cudaFuncAttributeMaxDynamicSharedMemorySize, SM_TOTAL);

    conv_kernel<<<CONV_A_BLKS + CONV_W_BLKS, 256>>>(enc, W);

    dim3 gg(NTILE, MTILE);   // 16 x 250
    gemm_tc<<<gg, 256, SM_TOTAL>>>(bias);

    lse_combine_kernel<<<(M_ + 255) / 256, 256>>>(lens);

    tail_kernel<<<B_ + T_ * (B_ / 2), 256>>>(targets, lens, tlens);

    finalize_kernel<<<1, 1>>>(out);
}

// round 14
// speedup vs baseline: 1.3337x; 1.3337x over previous
#include <cuda_runtime.h>
#include <cuda_bf16.h>
#include <cstdint>
#include <cstddef>

// Problem shape (fixed by the dataset)
constexpr int B_  = 32;
constexpr int T_  = 1000;
constexpr int C_  = 512;     // K
constexpr int V_  = 2000;    // N (logical)
constexpr int U_  = 100;
constexpr int S_  = 201;
constexpr int M_  = B_ * T_; // 32000
constexpr int NPAD = 2048;
constexpr float NEGF = -1.0e30f;

// GEMM tiling: BM=128 x BN=128 CTA tile, 8 warps (2m x 4n), warp tile 64x32.
// BK=32 (128B rows), 2 stages of 32KB -> 2 CTAs per SM. (R10 proven best)
constexpr int BM = 128;
constexpr int BN = 128;
constexpr int BK = 32;
constexpr int NSTG = C_ / BK;           // 16 k-stages
constexpr int NTILE = NPAD / BN;        // 16
constexpr int MTILE = M_ / BM;          // 250
constexpr int NPART = NTILE * 4;        // 64 lse partials

// smem: 2 stages x 32KB (A 16K + B 16K), bias after
constexpr int SM_STAGE = 32768;
constexpr int SM_BIAS  = 1024 + 2 * SM_STAGE;        // 66560
constexpr int SM_TOTAL = SM_BIAS + 512;              // 67072 (2 CTAs = 134KB/SM)

// -------- scratch (device globals: no allocations allowed) --------
__device__ __align__(256) float    g_logits[(size_t)M_ * V_];   // 256 MB
__device__ __align__(256) uint32_t g_At[(size_t)M_ * C_];       // tf32 bits (rna)
__device__ __align__(256) uint32_t g_Wt[(size_t)NPAD * C_];     // tf32 bits (rna)
__device__ float  g_pmax[NPART][M_];
__device__ float  g_psum[NPART][M_];
__device__ float  g_lse[M_];
__device__ double g_lsesum[B_];          // per-seq sum of lse over t < len
__device__ double g_ctc_acc;
__device__ double g_cr_acc;

// ===================== PTX helpers =====================
__device__ __forceinline__ uint32_t s2u(const void* p) {
    uint32_t a;
    asm("{ .reg .u64 t; cvta.to.shared.u64 t, %1; cvt.u32.u64 %0, t; }" : "=r"(a) : "l"(p));
    return a;
}
__device__ __forceinline__ void cpasync16(uint32_t dst, const void* src) {
    asm volatile("cp.async.cg.shared.global [%0], [%1], 16;" :: "r"(dst), "l"(src) : "memory");
}
__device__ __forceinline__ void ldsm4(uint32_t* r, uint32_t addr) {
    asm volatile("ldmatrix.sync.aligned.m8n8.x4.shared.b16 {%0,%1,%2,%3}, [%4];"
                 : "=r"(r[0]), "=r"(r[1]), "=r"(r[2]), "=r"(r[3]) : "r"(addr));
}
__device__ __forceinline__ void mma_tf32(float* d, const uint32_t* a, const uint32_t* b) {
    asm volatile(
        "mma.sync.aligned.m16n8k8.row.col.f32.tf32.tf32.f32 "
        "{%0,%1,%2,%3}, {%4,%5,%6,%7}, {%8,%9}, {%0,%1,%2,%3};"
        : "+f"(d[0]), "+f"(d[1]), "+f"(d[2]), "+f"(d[3])
        : "r"(a[0]), "r"(a[1]), "r"(a[2]), "r"(a[3]), "r"(b[0]), "r"(b[1]));
}
__device__ __forceinline__ uint32_t f2tf(float f) {
    uint32_t r;
    asm("cvt.rna.tf32.f32 %0, %1;" : "=r"(r) : "f"(f));
    return r;
}

// ===================== tf32 conversion (rna = unbiased), A+W fused ==========
constexpr int CONV_A_BLKS = (int)((size_t)M_ * C_ / 4 / 256);     // 16000
constexpr int CONV_W_BLKS = (int)((size_t)NPAD * C_ / 4 / 256);   // 1024

__global__ __launch_bounds__(256) void conv_kernel(const float* __restrict__ enc,
                                                   const float* __restrict__ W) {
    if (blockIdx.x == 0) {
        if (threadIdx.x == 0) { g_ctc_acc = 0.0; g_cr_acc = 0.0; }
        if (threadIdx.x < B_) g_lsesum[threadIdx.x] = 0.0;
    }
    if (blockIdx.x < CONV_A_BLKS) {
        size_t i = (size_t)blockIdx.x * 256 + threadIdx.x;
        float4 v = reinterpret_cast<const float4*>(enc)[i];
        uint4 o = make_uint4(f2tf(v.x), f2tf(v.y), f2tf(v.z), f2tf(v.w));
        reinterpret_cast<uint4*>(g_At)[i] = o;
    } else {
        size_t i = (size_t)(blockIdx.x - CONV_A_BLKS) * 256 + threadIdx.x;
        int row = (int)(i >> 7);
        float4 v = make_float4(0.f, 0.f, 0.f, 0.f);
        if (row < V_) v = reinterpret_cast<const float4*>(W)[i];
        uint4 o = make_uint4(f2tf(v.x), f2tf(v.y), f2tf(v.z), f2tf(v.w));
        reinterpret_cast<uint4*>(g_Wt)[i] = o;
    }
}

// ===================== TF32 HMMA GEMM + fused LSE partials =====================
// (R10 configuration: 2 stages, distance-1, 2 CTAs/SM — measured best)
__global__ __launch_bounds__(256, 2) void gemm_tc(const float* __restrict__ bias) {
    extern __shared__ __align__(1024) char smem[];
    const uint32_t sbase = s2u(smem);
    const int tid  = threadIdx.x;
    const int lane = tid & 31;
    const int wid  = tid >> 5;
    const int wm   = (wid >> 2) * 64;
    const int wn   = (wid & 3) * 32;
    const int n0   = blockIdx.x * BN;
    const int m0   = blockIdx.y * BM;

    float* sbias = reinterpret_cast<float*>(smem + SM_BIAS);
    if (tid < BN) sbias[tid] = (n0 + tid < V_) ? __ldg(&bias[n0 + tid]) : 0.f;

    auto issue_loads = [&](int s) {
        const uint32_t buf = sbase + 1024 + (uint32_t)(s & 1) * SM_STAGE;
        const int kt = s * BK;
#pragma unroll
        for (int i = 0; i < 4; i++) {
            int flat = tid + i * 256;
            int row = flat >> 3, cc = flat & 7;
            uint32_t off = (uint32_t)(row * 128 + ((cc * 16) ^ ((row & 7) << 4)));
            cpasync16(buf + off, &g_At[(size_t)(m0 + row) * C_ + kt + cc * 4]);
        }
#pragma unroll
        for (int i = 0; i < 4; i++) {
            int flat = tid + i * 256;
            int row = flat >> 3, cc = flat & 7;
            uint32_t off = (uint32_t)(row * 128 + ((cc * 16) ^ ((row & 7) << 4)));
            cpasync16(buf + 16384 + off, &g_Wt[(size_t)(n0 + row) * C_ + kt + cc * 4]);
        }
        asm volatile("cp.async.commit_group;" ::: "memory");
    };

    float acc[4][4][4];
#pragma unroll
    for (int i = 0; i < 4; i++)
#pragma unroll
        for (int j = 0; j < 4; j++)
#pragma unroll
            for (int e = 0; e < 4; e++) acc[i][j][e] = 0.f;

    const uint32_t xr = (uint32_t)((lane & 7) << 4);
    uint32_t offA[4], offB4[2];
#pragma unroll
    for (int mi = 0; mi < 4; mi++) offA[mi] = (uint32_t)((wm + mi * 16 + (lane & 15)) * 128);
#pragma unroll
    for (int p = 0; p < 2; p++)
        offB4[p] = (uint32_t)((wn + p * 16 + ((lane & 16) >> 1) + (lane & 7)) * 128);
    const uint32_t selA = (uint32_t)(lane & 16);
    const uint32_t selB = (uint32_t)((lane & 8) << 1);

    issue_loads(0);

    for (int s = 0; s < NSTG; s++) {
        asm volatile("cp.async.wait_group 0;" ::: "memory");
        __syncthreads();

        const uint32_t stgA = sbase + 1024 + (uint32_t)(s & 1) * SM_STAGE;
        const uint32_t stgB = stgA + 16384;

        uint32_t fa[4][4], fb[2][2][4];
        auto ldfragB = [&](int ks, int pb) {
            const uint32_t cB = ((uint32_t)(ks * 32) + selB) ^ xr;
#pragma unroll
            for (int p = 0; p < 2; p++) ldsm4(fb[pb][p], stgB + offB4[p] + cB);
        };

        ldfragB(0, 0);
        if (s + 1 < NSTG) issue_loads(s + 1);

#pragma unroll
        for (int ks = 0; ks < 4; ks++) {
            const uint32_t cA = ((uint32_t)(ks * 32) + selA) ^ xr;
#pragma unroll
            for (int mi = 0; mi < 4; mi++) ldsm4(fa[mi], stgA + offA[mi] + cA);
            if (ks < 3) ldfragB(ks + 1, (ks + 1) & 1);
#pragma unroll
            for (int mi = 0; mi < 4; mi++)
#pragma unroll
                for (int nj = 0; nj < 4; nj++)
                    mma_tf32(acc[mi][nj], fa[mi],
                             &fb[ks & 1][nj >> 1][(nj & 1) * 2]);
        }
    }

    // ---- epilogue: bias + direct store + fused row max/sumexp partials ----
    const int pn = blockIdx.x * 4 + (wid & 3);
    const int q  = lane >> 2;
    const int c2 = 2 * (lane & 3);

#pragma unroll
    for (int mi = 0; mi < 4; mi++) {
        float mx0 = NEGF, sm0 = 0.f;
        float mx1 = NEGF, sm1 = 0.f;
#pragma unroll
        for (int nj = 0; nj < 4; nj++) {
            int nloc = wn + nj * 8 + c2;
            int n = n0 + nloc;
            float b0 = sbias[nloc], b1 = sbias[nloc + 1];
            float v00 = acc[mi][nj][0] + b0, v01 = acc[mi][nj][1] + b1;
            float v10 = acc[mi][nj][2] + b0, v11 = acc[mi][nj][3] + b1;
            if (n < V_) {
                int mr = m0 + wm + mi * 16 + q;
                *reinterpret_cast<float2*>(&g_logits[(size_t)mr * V_ + n])       = make_float2(v00, v01);
                *reinterpret_cast<float2*>(&g_logits[(size_t)(mr + 8) * V_ + n]) = make_float2(v10, v11);
                float a = fmaxf(v00, v01);
                if (a > mx0) { sm0 *= __expf(mx0 - a); mx0 = a; }
                sm0 += __expf(v00 - mx0) + __expf(v01 - mx0);
                float b = fmaxf(v10, v11);
                if (b > mx1) { sm1 *= __expf(mx1 - b); mx1 = b; }
                sm1 += __expf(v10 - mx1) + __expf(v11 - mx1);
            }
        }
#pragma unroll
        for (int d = 1; d <= 2; d <<= 1) {
            float mo = __shfl_xor_sync(0xffffffffu, mx0, d);
            float so = __shfl_xor_sync(0xffffffffu, sm0, d);
            float M = fmaxf(mx0, mo);
            sm0 = sm0 * __expf(mx0 - M) + so * __expf(mo - M);
            mx0 = M;
            mo = __shfl_xor_sync(0xffffffffu, mx1, d);
            so = __shfl_xor_sync(0xffffffffu, sm1, d);
            M = fmaxf(mx1, mo);
            sm1 = sm1 * __expf(mx1 - M) + so * __expf(mo - M);
            mx1 = M;
        }
        if ((lane & 3) == 0) {
            int mr = m0 + wm + mi * 16 + q;
            g_pmax[pn][mr]     = mx0;  g_psum[pn][mr]     = sm0;
            g_pmax[pn][mr + 8] = mx1;  g_psum[pn][mr + 8] = sm1;
        }
    }
}

// ===================== LSE combine (+ per-seq lse sums) =====================
__global__ __launch_bounds__(256) void lse_combine_kernel(const int* __restrict__ lens) {
    int m = blockIdx.x * 256 + threadIdx.x;
    if (m >= M_) return;
    float mx = NEGF;
#pragma unroll
    for (int p = 0; p < NPART; p++) mx = fmaxf(mx, g_pmax[p][m]);
    float s = 0.f;
#pragma unroll
    for (int p = 0; p < NPART; p++) s += g_psum[p][m] * __expf(g_pmax[p][m] - mx);
    float val = mx + __logf(s);
    g_lse[m] = val;

    // accumulate S_b = sum of lse over t < len (warp-aggregated double atomics)
    int b = m / T_, t = m % T_;
    double contrib = (t < lens[b]) ? (double)val : 0.0;
    int b0 = __shfl_sync(0xffffffffu, b, 0);
    int b31 = __shfl_sync(0xffffffffu, b, 31);
    if (b0 == b31) {
#pragma unroll
        for (int o = 16; o > 0; o >>= 1)
            contrib += __shfl_down_sync(0xffffffffu, contrib, o);
        if ((threadIdx.x & 31) == 0 && contrib != 0.0) atomicAdd(&g_lsesum[b], contrib);
    } else {
        if (contrib != 0.0) atomicAdd(&g_lsesum[b], contrib);
    }
}

// ===================== fused tail: CTC (blocks 0..31) + KL (rest) ==========
__device__ __forceinline__ float logadd3(float a, float b, float c) {
    float m = fmaxf(a, fmaxf(b, c));
    return m + __logf(__expf(a - m) + __expf(b - m) + __expf(c - m));
}
__device__ __forceinline__ float logadd2(float a, float b) {
    float m = fmaxf(a, b);
    return m + __logf(__expf(a - m) + __expf(b - m));
}

// CTC on RAW logits (lse factored out exactly; applied once via g_lsesum).
// REGISTER prefetch rings only — no STS near the barrier (BAR drains STS!).
// e0/e1/e2 are loop-invariant registers.
__device__ void ctc_body(int b, const int* __restrict__ targets,
                         const int* __restrict__ lens, const int* __restrict__ tlens) {
    const int s = threadIdx.x;           // 0..255 (states >= S_ are inert)
    const int len = lens[b];

    __shared__ float alpha[2][256 + 4];  // 4-element NEGF pad at the front
    if (s < 4) { alpha[0][s] = NEGF; alpha[1][s] = NEGF; }

    const int* tg = &targets[b * U_];
    bool v0 = (s < S_), v1 = (s >= 1 && s - 1 < S_), v2 = (s >= 2 && s - 2 < S_);
    int e0 = 0, e1 = 0, e2 = 0;
    if (v0 && (s & 1))            e0 = tg[(s - 1) >> 1];
    if (v1 && ((s - 1) & 1))      e1 = tg[(s - 2) >> 1];
    if (v2 && (s & 1) && s >= 3)  e2 = tg[(s - 3) >> 1];

    bool sk0 = false, sk1 = false, sk2 = false;
    if (s < S_) {
        if (s & 1) {
            int i = (s - 1) >> 1;
            if (s >= 3) sk0 = tg[i] != tg[i - 1];
            if (s >= 5) sk2 = tg[i - 1] != tg[i - 2];
        } else {
            if (s >= 4) sk1 = tg[(s - 2) >> 1] != tg[(s - 4) >> 1];
        }
    }

    const size_t rowbase = (size_t)(b * T_);
    alpha[0][4 + s] = (s < 2) ? g_logits[rowbase * V_ + e0] : NEGF;
    __syncthreads();

    // register prefetch ring: 4 pair-slots = 8 time steps ahead; static indices
    float p0[4], p1[4], p2[4], pB[4];
#pragma unroll
    for (int jj = 0; jj < 4; jj++) {
        int ta = 1 + 2 * jj;
        int tb = ta + 1 < T_ ? ta + 1 : T_ - 1;
        const float* ra = &g_logits[(rowbase + ta) * V_];
        const float* rb = &g_logits[(rowbase + tb) * V_];
        p0[jj] = v0 ? ra[e0] : NEGF;
        p1[jj] = v1 ? ra[e1] : NEGF;
        p2[jj] = v2 ? ra[e2] : NEGF;
        pB[jj] = v0 ? rb[e0] : NEGF;
    }

    int cur = 0;
    for (int t0 = 1; t0 < len; t0 += 8) {
#pragma unroll
        for (int jj = 0; jj < 4; jj++) {
            const int t = t0 + 2 * jj;
            const float* Aa = &alpha[cur][4];
            float a0 = Aa[s], a1 = Aa[s - 1], a2 = Aa[s - 2], a3 = Aa[s - 3], a4 = Aa[s - 4];

            float x0 = logadd3(a0, a1, sk0 ? a2 : NEGF) + p0[jj];
            float x1 = logadd3(a1, a2, sk1 ? a3 : NEGF) + p1[jj];
            float x2 = logadd3(a2, a3, sk2 ? a4 : NEGF) + p2[jj];
            float yf = logadd3(x0, x1, sk0 ? x2 : NEGF) + pB[jj];
            float y  = (t >= len) ? a0 : ((t + 1 >= len) ? x0 : yf);

            alpha[cur ^ 1][4 + s] = y;
            cur ^= 1;
            __syncthreads();

            // refill slot jj for time t+8 (registers only; consumed 4 iters later)
            int tn = t + 8;
            int ta = tn < T_ ? tn : T_ - 1;
            int tb = tn + 1 < T_ ? tn + 1 : T_ - 1;
            const float* ra = &g_logits[(rowbase + ta) * V_];
            const float* rb = &g_logits[(rowbase + tb) * V_];
            p0[jj] = v0 ? ra[e0] : NEGF;
            p1[jj] = v1 ? ra[e1] : NEGF;
            p2[jj] = v2 ? ra[e2] : NEGF;
            pB[jj] = v0 ? rb[e0] : NEGF;
        }
    }

    if (s == 0) {
        int e = 2 * tlens[b];
        float ab = alpha[cur][4 + e];
        float al = alpha[cur][4 + (e > 0 ? e - 1 : 0)];
        double loss = g_lsesum[b] - (double)logadd2(ab, al);
        atomicAdd(&g_ctc_acc, loss);
    }
}

__device__ void kl_body(int idx, const int* __restrict__ lens) {
    const int t  = idx % T_;
    const int bp = idx / T_;
    const int lenA = lens[bp], lenB = lens[bp + 16];
    const bool doA = t < lenA, doB = t < lenB;
    if (!doA && !doB) return;

    const size_t rowP = (size_t)bp * T_ + t;
    const size_t rowQ = (size_t)(bp + 16) * T_ + t;
    const float* P = &g_logits[rowP * V_];
    const float* Q = &g_logits[rowQ * V_];
    const float Lp = g_lse[rowP], Lq = g_lse[rowQ];

    float accA = 0.f, accB = 0.f;
#pragma unroll 8
    for (int v = threadIdx.x; v < V_; v += 256) {
        float p = P[v] - Lp;
        float q = Q[v] - Lq;
        float d = q - p;
        accA += __expf(q) * d;
        accB -= __expf(p) * d;
    }
    float c = (doA ? accA : 0.f) + (doB ? accB : 0.f);
    for (int o = 16; o > 0; o >>= 1) c += __shfl_down_sync(0xffffffffu, c, o);
    __shared__ float wsum[8];
    if ((threadIdx.x & 31) == 0) wsum[threadIdx.x >> 5] = c;
    __syncthreads();
    if (threadIdx.x == 0) {
        float tot = 0.f;
#pragma unroll
        for (int w = 0; w < 8; w++) tot += wsum[w];
        atomicAdd(&g_cr_acc, (double)tot);
    }
}

__global__ __launch_bounds__(256) void tail_kernel(const int* __restrict__ targets,
                                                   const int* __restrict__ lens,
                                                   const int* __restrict__ tlens) {
    if (blockIdx.x < (unsigned)B_) ctc_body(blockIdx.x, targets, lens, tlens);
    else                            kl_body(blockIdx.x - B_, lens);
}

// ===================== finalize =====================
__global__ void finalize_kernel(float* out) {
    out[0] = (float)(0.5 * g_ctc_acc);
    out[1] = (float)(0.5 * g_cr_acc);
}

// ===================== launch =====================
extern "C" void kernel_launch(void* const* d_in, const int* in_sizes, int n_in,
                              void* d_out, int out_size) {
    const float* enc     = (const float*)d_in[0];
    const float* W       = (const float*)d_in[1];
    const float* bias    = (const float*)d_in[2];
    const int*   lens    = (const int*)d_in[3];
    const int*   targets = (const int*)d_in[4];
    const int*   tlens   = (const int*)d_in[5];
    float* out = (float*)d_out;

    cudaFuncSetAttribute(gemm_tc, cudaFuncAttributeMaxDynamicSharedMemorySize, SM_TOTAL);

    conv_kernel<<<CONV_A_BLKS + CONV_W_BLKS, 256>>>(enc, W);

    dim3 gg(NTILE, MTILE);   // 16 x 250
    gemm_tc<<<gg, 256, SM_TOTAL>>>(bias);

    lse_combine_kernel<<<(M_ + 255) / 256, 256>>>(lens);

    tail_kernel<<<B_ + T_ * (B_ / 2), 256>>>(targets, lens, tlens);

    finalize_kernel<<<1, 1>>>(out);
}

// round 15
// speedup vs baseline: 1.5600x; 1.1697x over previous
#include <cuda_runtime.h>
#include <cuda_bf16.h>
#include <cstdint>
#include <cstddef>

// Problem shape (fixed by the dataset)
constexpr int B_  = 32;
constexpr int T_  = 1000;
constexpr int C_  = 512;     // K
constexpr int V_  = 2000;    // N (logical)
constexpr int U_  = 100;
constexpr int S_  = 201;
constexpr int M_  = B_ * T_; // 32000
constexpr int NPAD = 2048;
constexpr float NEGF = -1.0e30f;

// GEMM tiling: BM=128 x BN=128 CTA tile, 8 warps (2m x 4n), warp tile 64x32.
// BK=32 (128B rows), 2 stages of 32KB -> 2 CTAs per SM. (R10 proven best)
constexpr int BM = 128;
constexpr int BN = 128;
constexpr int BK = 32;
constexpr int NSTG = C_ / BK;           // 16 k-stages
constexpr int NTILE = NPAD / BN;        // 16
constexpr int MTILE = M_ / BM;          // 250
constexpr int NPART = NTILE * 4;        // 64 lse partials

// smem: 2 stages x 32KB (A 16K + B 16K), bias after
constexpr int SM_STAGE = 32768;
constexpr int SM_BIAS  = 1024 + 2 * SM_STAGE;        // 66560
constexpr int SM_TOTAL = SM_BIAS + 512;              // 67072 (2 CTAs = 134KB/SM)

// -------- scratch (device globals: no allocations allowed) --------
__device__ __align__(256) float    g_logits[(size_t)M_ * V_];   // 256 MB
__device__ __align__(256) uint32_t g_At[(size_t)M_ * C_];       // tf32 bits (rna)
__device__ __align__(256) uint32_t g_Wt[(size_t)NPAD * C_];     // tf32 bits (rna)
__device__ float  g_pmax[NPART][M_];
__device__ float  g_psum[NPART][M_];
__device__ float  g_lse[M_];
__device__ double g_lsesum[B_];          // per-seq sum of lse over t < len
__device__ double g_ctc_acc;
__device__ double g_cr_acc;

// ===================== PTX helpers =====================
__device__ __forceinline__ uint32_t s2u(const void* p) {
    uint32_t a;
    asm("{ .reg .u64 t; cvta.to.shared.u64 t, %1; cvt.u32.u64 %0, t; }" : "=r"(a) : "l"(p));
    return a;
}
__device__ __forceinline__ void cpasync16(uint32_t dst, const void* src) {
    asm volatile("cp.async.cg.shared.global [%0], [%1], 16;" :: "r"(dst), "l"(src) : "memory");
}
__device__ __forceinline__ void ldsm4(uint32_t* r, uint32_t addr) {
    asm volatile("ldmatrix.sync.aligned.m8n8.x4.shared.b16 {%0,%1,%2,%3}, [%4];"
                 : "=r"(r[0]), "=r"(r[1]), "=r"(r[2]), "=r"(r[3]) : "r"(addr));
}
__device__ __forceinline__ void mma_tf32(float* d, const uint32_t* a, const uint32_t* b) {
    asm volatile(
        "mma.sync.aligned.m16n8k8.row.col.f32.tf32.tf32.f32 "
        "{%0,%1,%2,%3}, {%4,%5,%6,%7}, {%8,%9}, {%0,%1,%2,%3};"
        : "+f"(d[0]), "+f"(d[1]), "+f"(d[2]), "+f"(d[3])
        : "r"(a[0]), "r"(a[1]), "r"(a[2]), "r"(a[3]), "r"(b[0]), "r"(b[1]));
}
__device__ __forceinline__ uint32_t f2tf(float f) {
    uint32_t r;
    asm("cvt.rna.tf32.f32 %0, %1;" : "=r"(r) : "f"(f));
    return r;
}

// ===================== tf32 conversion (rna = unbiased), A+W fused ==========
constexpr int CONV_A_BLKS = (int)((size_t)M_ * C_ / 4 / 256);     // 16000
constexpr int CONV_W_BLKS = (int)((size_t)NPAD * C_ / 4 / 256);   // 1024

__global__ __launch_bounds__(256) void conv_kernel(const float* __restrict__ enc,
                                                   const float* __restrict__ W) {
    if (blockIdx.x == 0) {
        if (threadIdx.x == 0) { g_ctc_acc = 0.0; g_cr_acc = 0.0; }
        if (threadIdx.x < B_) g_lsesum[threadIdx.x] = 0.0;
    }
    if (blockIdx.x < CONV_A_BLKS) {
        size_t i = (size_t)blockIdx.x * 256 + threadIdx.x;
        float4 v = reinterpret_cast<const float4*>(enc)[i];
        uint4 o = make_uint4(f2tf(v.x), f2tf(v.y), f2tf(v.z), f2tf(v.w));
        reinterpret_cast<uint4*>(g_At)[i] = o;
    } else {
        size_t i = (size_t)(blockIdx.x - CONV_A_BLKS) * 256 + threadIdx.x;
        int row = (int)(i >> 7);
        float4 v = make_float4(0.f, 0.f, 0.f, 0.f);
        if (row < V_) v = reinterpret_cast<const float4*>(W)[i];
        uint4 o = make_uint4(f2tf(v.x), f2tf(v.y), f2tf(v.z), f2tf(v.w));
        reinterpret_cast<uint4*>(g_Wt)[i] = o;
    }
}

// ===================== TF32 HMMA GEMM + fused LSE partials =====================
// (R10 configuration: 2 stages, distance-1, 2 CTAs/SM — measured best)
__global__ __launch_bounds__(256, 2) void gemm_tc(const float* __restrict__ bias) {
    extern __shared__ __align__(1024) char smem[];
    const uint32_t sbase = s2u(smem);
    const int tid  = threadIdx.x;
    const int lane = tid & 31;
    const int wid  = tid >> 5;
    const int wm   = (wid >> 2) * 64;
    const int wn   = (wid & 3) * 32;
    const int n0   = blockIdx.x * BN;
    const int m0   = blockIdx.y * BM;

    float* sbias = reinterpret_cast<float*>(smem + SM_BIAS);
    if (tid < BN) sbias[tid] = (n0 + tid < V_) ? __ldg(&bias[n0 + tid]) : 0.f;

    auto issue_loads = [&](int s) {
        const uint32_t buf = sbase + 1024 + (uint32_t)(s & 1) * SM_STAGE;
        const int kt = s * BK;
#pragma unroll
        for (int i = 0; i < 4; i++) {
            int flat = tid + i * 256;
            int row = flat >> 3, cc = flat & 7;
            uint32_t off = (uint32_t)(row * 128 + ((cc * 16) ^ ((row & 7) << 4)));
            cpasync16(buf + off, &g_At[(size_t)(m0 + row) * C_ + kt + cc * 4]);
        }
#pragma unroll
        for (int i = 0; i < 4; i++) {
            int flat = tid + i * 256;
            int row = flat >> 3, cc = flat & 7;
            uint32_t off = (uint32_t)(row * 128 + ((cc * 16) ^ ((row & 7) << 4)));
            cpasync16(buf + 16384 + off, &g_Wt[(size_t)(n0 + row) * C_ + kt + cc * 4]);
        }
        asm volatile("cp.async.commit_group;" ::: "memory");
    };

    float acc[4][4][4];
#pragma unroll
    for (int i = 0; i < 4; i++)
#pragma unroll
        for (int j = 0; j < 4; j++)
#pragma unroll
            for (int e = 0; e < 4; e++) acc[i][j][e] = 0.f;

    const uint32_t xr = (uint32_t)((lane & 7) << 4);
    uint32_t offA[4], offB4[2];
#pragma unroll
    for (int mi = 0; mi < 4; mi++) offA[mi] = (uint32_t)((wm + mi * 16 + (lane & 15)) * 128);
#pragma unroll
    for (int p = 0; p < 2; p++)
        offB4[p] = (uint32_t)((wn + p * 16 + ((lane & 16) >> 1) + (lane & 7)) * 128);
    const uint32_t selA = (uint32_t)(lane & 16);
    const uint32_t selB = (uint32_t)((lane & 8) << 1);

    issue_loads(0);

    for (int s = 0; s < NSTG; s++) {
        asm volatile("cp.async.wait_group 0;" ::: "memory");
        __syncthreads();

        const uint32_t stgA = sbase + 1024 + (uint32_t)(s & 1) * SM_STAGE;
        const uint32_t stgB = stgA + 16384;

        uint32_t fa[4][4], fb[2][2][4];
        auto ldfragB = [&](int ks, int pb) {
            const uint32_t cB = ((uint32_t)(ks * 32) + selB) ^ xr;
#pragma unroll
            for (int p = 0; p < 2; p++) ldsm4(fb[pb][p], stgB + offB4[p] + cB);
        };

        ldfragB(0, 0);
        if (s + 1 < NSTG) issue_loads(s + 1);

#pragma unroll
        for (int ks = 0; ks < 4; ks++) {
            const uint32_t cA = ((uint32_t)(ks * 32) + selA) ^ xr;
#pragma unroll
            for (int mi = 0; mi < 4; mi++) ldsm4(fa[mi], stgA + offA[mi] + cA);
            if (ks < 3) ldfragB(ks + 1, (ks + 1) & 1);
#pragma unroll
            for (int mi = 0; mi < 4; mi++)
#pragma unroll
                for (int nj = 0; nj < 4; nj++)
                    mma_tf32(acc[mi][nj], fa[mi],
                             &fb[ks & 1][nj >> 1][(nj & 1) * 2]);
        }
    }

    // ---- epilogue: bias + direct store + fused row max/sumexp partials ----
    const int pn = blockIdx.x * 4 + (wid & 3);
    const int q  = lane >> 2;
    const int c2 = 2 * (lane & 3);

#pragma unroll
    for (int mi = 0; mi < 4; mi++) {
        float mx0 = NEGF, sm0 = 0.f;
        float mx1 = NEGF, sm1 = 0.f;
#pragma unroll
        for (int nj = 0; nj < 4; nj++) {
            int nloc = wn + nj * 8 + c2;
            int n = n0 + nloc;
            float b0 = sbias[nloc], b1 = sbias[nloc + 1];
            float v00 = acc[mi][nj][0] + b0, v01 = acc[mi][nj][1] + b1;
            float v10 = acc[mi][nj][2] + b0, v11 = acc[mi][nj][3] + b1;
            if (n < V_) {
                int mr = m0 + wm + mi * 16 + q;
                *reinterpret_cast<float2*>(&g_logits[(size_t)mr * V_ + n])       = make_float2(v00, v01);
                *reinterpret_cast<float2*>(&g_logits[(size_t)(mr + 8) * V_ + n]) = make_float2(v10, v11);
                float a = fmaxf(v00, v01);
                if (a > mx0) { sm0 *= __expf(mx0 - a); mx0 = a; }
                sm0 += __expf(v00 - mx0) + __expf(v01 - mx0);
                float b = fmaxf(v10, v11);
                if (b > mx1) { sm1 *= __expf(mx1 - b); mx1 = b; }
                sm1 += __expf(v10 - mx1) + __expf(v11 - mx1);
            }
        }
#pragma unroll
        for (int d = 1; d <= 2; d <<= 1) {
            float mo = __shfl_xor_sync(0xffffffffu, mx0, d);
            float so = __shfl_xor_sync(0xffffffffu, sm0, d);
            float M = fmaxf(mx0, mo);
            sm0 = sm0 * __expf(mx0 - M) + so * __expf(mo - M);
            mx0 = M;
            mo = __shfl_xor_sync(0xffffffffu, mx1, d);
            so = __shfl_xor_sync(0xffffffffu, sm1, d);
            M = fmaxf(mx1, mo);
            sm1 = sm1 * __expf(mx1 - M) + so * __expf(mo - M);
            mx1 = M;
        }
        if ((lane & 3) == 0) {
            int mr = m0 + wm + mi * 16 + q;
            g_pmax[pn][mr]     = mx0;  g_psum[pn][mr]     = sm0;
            g_pmax[pn][mr + 8] = mx1;  g_psum[pn][mr + 8] = sm1;
        }
    }
}

// ===================== LSE combine (+ per-seq lse sums) =====================
__global__ __launch_bounds__(256) void lse_combine_kernel(const int* __restrict__ lens) {
    int m = blockIdx.x * 256 + threadIdx.x;
    if (m >= M_) return;
    float mx = NEGF;
#pragma unroll
    for (int p = 0; p < NPART; p++) mx = fmaxf(mx, g_pmax[p][m]);
    float s = 0.f;
#pragma unroll
    for (int p = 0; p < NPART; p++) s += g_psum[p][m] * __expf(g_pmax[p][m] - mx);
    float val = mx + __logf(s);
    g_lse[m] = val;

    // accumulate S_b = sum of lse over t < len (warp-aggregated double atomics)
    int b = m / T_, t = m % T_;
    double contrib = (t < lens[b]) ? (double)val : 0.0;
    int b0 = __shfl_sync(0xffffffffu, b, 0);
    int b31 = __shfl_sync(0xffffffffu, b, 31);
    if (b0 == b31) {
#pragma unroll
        for (int o = 16; o > 0; o >>= 1)
            contrib += __shfl_down_sync(0xffffffffu, contrib, o);
        if ((threadIdx.x & 31) == 0 && contrib != 0.0) atomicAdd(&g_lsesum[b], contrib);
    } else {
        if (contrib != 0.0) atomicAdd(&g_lsesum[b], contrib);
    }
}

// ===================== fused tail: CTC (blocks 0..31) + KL (rest) ==========
__device__ __forceinline__ float logadd3(float a, float b, float c) {
    float m = fmaxf(a, fmaxf(b, c));
    return m + __logf(__expf(a - m) + __expf(b - m) + __expf(c - m));
}
__device__ __forceinline__ float logadd2(float a, float b) {
    float m = fmaxf(a, b);
    return m + __logf(__expf(a - m) + __expf(b - m));
}

// CTC on RAW logits (lse factored out exactly; applied once via g_lsesum).
// ONE logadd3 per step per thread (minimal MUFU — the measured binder),
// barrier per step, 8-slot REGISTER prefetch ring (no STS near barriers).
__device__ void ctc_body(int b, const int* __restrict__ targets,
                         const int* __restrict__ lens, const int* __restrict__ tlens) {
    const int s = threadIdx.x;           // 0..255 (states >= S_ are inert)
    const int len = lens[b];

    __shared__ float alpha[2][256 + 4];  // 4-element NEGF pad at the front
    if (s < 4) { alpha[0][s] = NEGF; alpha[1][s] = NEGF; }

    const int* tg = &targets[b * U_];
    const bool v0 = (s < S_);
    int e0 = 0;
    if (v0 && (s & 1)) e0 = tg[(s - 1) >> 1];

    bool sk0 = false;
    if (s < S_ && (s & 1) && s >= 3) {
        int i = (s - 1) >> 1;
        sk0 = tg[i] != tg[i - 1];
    }

    const size_t rowbase = (size_t)(b * T_);
    alpha[0][4 + s] = (s < 2) ? g_logits[rowbase * V_ + e0] : NEGF;
    __syncthreads();

    // register prefetch ring: 8 slots = 8 time steps ahead; static indices
    float pre[8];
#pragma unroll
    for (int j = 0; j < 8; j++) {
        int ta = 1 + j; if (ta >= T_) ta = T_ - 1;
        pre[j] = v0 ? g_logits[(rowbase + ta) * V_ + e0] : NEGF;
    }

    int cur = 0;
    for (int t0 = 1; t0 < len; t0 += 8) {
#pragma unroll
        for (int j = 0; j < 8; j++) {
            const int t = t0 + j;
            const float* Aa = &alpha[cur][4];
            float a0 = Aa[s], a1 = Aa[s - 1], a2 = Aa[s - 2];

            float x = logadd3(a0, a1, sk0 ? a2 : NEGF) + pre[j];
            float y = (t < len) ? x : a0;

            alpha[cur ^ 1][4 + s] = y;
            cur ^= 1;
            __syncthreads();

            // refill slot j for time t+8 (register only; consumed 8 steps later)
            int tn = t + 8; if (tn >= T_) tn = T_ - 1;
            pre[j] = v0 ? g_logits[(rowbase + tn) * V_ + e0] : NEGF;
        }
    }

    if (s == 0) {
        int e = 2 * tlens[b];
        float ab = alpha[cur][4 + e];
        float al = alpha[cur][4 + (e > 0 ? e - 1 : 0)];
        double loss = g_lsesum[b] - (double)logadd2(ab, al);
        atomicAdd(&g_ctc_acc, loss);
    }
}

__device__ void kl_body(int idx, const int* __restrict__ lens) {
    const int t  = idx % T_;
    const int bp = idx / T_;
    const int lenA = lens[bp], lenB = lens[bp + 16];
    const bool doA = t < lenA, doB = t < lenB;
    if (!doA && !doB) return;

    const size_t rowP = (size_t)bp * T_ + t;
    const size_t rowQ = (size_t)(bp + 16) * T_ + t;
    const float* P = &g_logits[rowP * V_];
    const float* Q = &g_logits[rowQ * V_];
    const float Lp = g_lse[rowP], Lq = g_lse[rowQ];

    float accA = 0.f, accB = 0.f;
#pragma unroll 8
    for (int v = threadIdx.x; v < V_; v += 256) {
        float p = P[v] - Lp;
        float q = Q[v] - Lq;
        float d = q - p;
        accA += __expf(q) * d;
        accB -= __expf(p) * d;
    }
    float c = (doA ? accA : 0.f) + (doB ? accB : 0.f);
    for (int o = 16; o > 0; o >>= 1) c += __shfl_down_sync(0xffffffffu, c, o);
    __shared__ float wsum[8];
    if ((threadIdx.x & 31) == 0) wsum[threadIdx.x >> 5] = c;
    __syncthreads();
    if (threadIdx.x == 0) {
        float tot = 0.f;
#pragma unroll
        for (int w = 0; w < 8; w++) tot += wsum[w];
        atomicAdd(&g_cr_acc, (double)tot);
    }
}

__global__ __launch_bounds__(256) void tail_kernel(const int* __restrict__ targets,
                                                   const int* __restrict__ lens,
                                                   const int* __restrict__ tlens) {
    if (blockIdx.x < (unsigned)B_) ctc_body(blockIdx.x, targets, lens, tlens);
    else                            kl_body(blockIdx.x - B_, lens);
}

// ===================== finalize =====================
__global__ void finalize_kernel(float* out) {
    out[0] = (float)(0.5 * g_ctc_acc);
    out[1] = (float)(0.5 * g_cr_acc);
}

// ===================== launch =====================
extern "C" void kernel_launch(void* const* d_in, const int* in_sizes, int n_in,
                              void* d_out, int out_size) {
    const float* enc     = (const float*)d_in[0];
    const float* W       = (const float*)d_in[1];
    const float* bias    = (const float*)d_in[2];
    const int*   lens    = (const int*)d_in[3];
    const int*   targets = (const int*)d_in[4];
    const int*   tlens   = (const int*)d_in[5];
    float* out = (float*)d_out;

    cudaFuncSetAttribute(gemm_tc, cudaFuncAttributeMaxDynamicSharedMemorySize, SM_TOTAL);

    conv_kernel<<<CONV_A_BLKS + CONV_W_BLKS, 256>>>(enc, W);

    dim3 gg(NTILE, MTILE);   // 16 x 250
    gemm_tc<<<gg, 256, SM_TOTAL>>>(bias);

    lse_combine_kernel<<<(M_ + 255) / 256, 256>>>(lens);

    tail_kernel<<<B_ + T_ * (B_ / 2), 256>>>(targets, lens, tlens);

    finalize_kernel<<<1, 1>>>(out);
}